// round 1
// baseline (speedup 1.0000x reference)
#include <cuda_runtime.h>
#include <cstdint>
#include <cstddef>

#define LN 256
#define BN 128
#define DN 512
#define HN 512
#define G3 1536

// Scratch (static device globals — no allocations allowed in kernel_launch)
static __device__ float g_PXdt[(size_t)LN * BN * G3];   // emb @ dt_Wx + dt_b, [L,B,3H]
static __device__ float g_PXtd[(size_t)LN * BN * G3];   // emb @ td_Wx + td_b
static __device__ float g_acc[(size_t)BN * LN * HN];    // dt child-sum accumulator [B,L,H]
static __device__ float g_tds[(size_t)BN * LN * HN];    // td hidden state [B,L,H]
static __device__ unsigned g_barCount[2];
static __device__ volatile unsigned g_barGen[2];

// ---------------------------------------------------------------------------
// zero the dt accumulator (must be zero at the start of every replay)
// ---------------------------------------------------------------------------
__global__ void zero_acc_kernel() {
  size_t i = (size_t)blockIdx.x * blockDim.x + threadIdx.x;
  reinterpret_cast<float4*>(g_acc)[i] = make_float4(0.f, 0.f, 0.f, 0.f);
}

// ---------------------------------------------------------------------------
// SGEMM: C[M,1536] = A[M,512] @ W[512,1536] + bias   (fp32, 128x128x16 tiles)
// which == 0 -> g_PXdt, which == 1 -> g_PXtd
// ---------------------------------------------------------------------------
__global__ void __launch_bounds__(256) sgemm_px(
    const float* __restrict__ A, const float* __restrict__ W,
    const float* __restrict__ bias, int which)
{
  float* __restrict__ C = which ? g_PXtd : g_PXdt;
  __shared__ float As[16][132];   // transposed A tile, padded
  __shared__ float Bs[16][128];
  const int m0 = blockIdx.y << 7;
  const int n0 = blockIdx.x << 7;
  const int tid = threadIdx.x;
  const int ty = tid >> 4, tx = tid & 15;

  float acc[8][8];
#pragma unroll
  for (int i = 0; i < 8; ++i)
#pragma unroll
    for (int j = 0; j < 8; ++j) acc[i][j] = 0.f;

  for (int k0 = 0; k0 < DN; k0 += 16) {
#pragma unroll
    for (int i = 0; i < 2; ++i) {
      int idx = tid + (i << 8);
      int row = idx >> 2, kv = idx & 3;
      float4 va = *(const float4*)(A + (size_t)(m0 + row) * DN + k0 + (kv << 2));
      As[(kv << 2) + 0][row] = va.x;
      As[(kv << 2) + 1][row] = va.y;
      As[(kv << 2) + 2][row] = va.z;
      As[(kv << 2) + 3][row] = va.w;
      int kk = idx >> 5, cv = idx & 31;
      *(float4*)&Bs[kk][cv << 2] =
          *(const float4*)(W + (size_t)(k0 + kk) * G3 + n0 + (cv << 2));
    }
    __syncthreads();
#pragma unroll
    for (int k = 0; k < 16; ++k) {
      float a[8], b[8];
      *(float4*)&a[0] = *(const float4*)&As[k][(ty << 3)];
      *(float4*)&a[4] = *(const float4*)&As[k][(ty << 3) + 4];
      *(float4*)&b[0] = *(const float4*)&Bs[k][(tx << 3)];
      *(float4*)&b[4] = *(const float4*)&Bs[k][(tx << 3) + 4];
#pragma unroll
      for (int i = 0; i < 8; ++i)
#pragma unroll
        for (int j = 0; j < 8; ++j)
          acc[i][j] = fmaf(a[i], b[j], acc[i][j]);
    }
    __syncthreads();
  }

#pragma unroll
  for (int i = 0; i < 8; ++i) {
    size_t row = (size_t)m0 + (ty << 3) + i;
    float* cp = C + row * G3 + n0 + (tx << 3);
#pragma unroll
    for (int j = 0; j < 8; ++j)
      cp[j] = acc[i][j] + bias[n0 + (tx << 3) + j];
  }
}

// ---------------------------------------------------------------------------
// pass-local grid barrier (64 blocks per pass; all 128 blocks co-resident)
// ---------------------------------------------------------------------------
__device__ __forceinline__ void pass_barrier(int p, unsigned nb) {
  __syncthreads();
  if (threadIdx.x == 0) {
    __threadfence();                       // publish this block's writes
    unsigned g = g_barGen[p];
    unsigned a = atomicAdd(&g_barCount[p], 1u);
    if (a == nb - 1u) {
      g_barCount[p] = 0u;
      __threadfence();
      g_barGen[p] = g + 1u;
    } else {
      while (g_barGen[p] == g) { }
      __threadfence();                     // acquire
    }
  }
  __syncthreads();
}

// ---------------------------------------------------------------------------
// Persistent recurrent kernel: 128 blocks (64 dt + 64 td), 256 threads.
// Per pass per step: hg = h @ Uh with h gathered/scattered by tree structure,
// fused GRU gates. Block = 64 batches x 16 hidden cols (x3 gate thirds).
// ---------------------------------------------------------------------------
__global__ void __launch_bounds__(256) recurrent_kernel(
    const int* __restrict__ indexes,
    const int* __restrict__ td_node,
    const int* __restrict__ td_parent_idx,
    const float* __restrict__ td_parent_valid,
    const float* __restrict__ dt_Uh,
    const float* __restrict__ td_Uh,
    float* __restrict__ out)
{
  const int blk = blockIdx.x;
  const int pass = blk >> 6;            // 0 = bottom-up (dt), 1 = top-down (td)
  const int lb = blk & 63;
  const int mb = (lb & 1) << 6;         // batch tile base (0 or 64)
  const int c0 = (lb >> 1) << 4;        // hidden col tile base (0..496)

  const float* __restrict__ Uh = pass ? td_Uh : dt_Uh;
  const float* __restrict__ PX = pass ? g_PXtd : g_PXdt;

  __shared__ float As[16][68];          // [k][row] transposed h tile
  __shared__ float Bs[16][48];          // [k][g*16 + c] Uh tile, 3 gate thirds
  __shared__ int sNode[64];
  __shared__ int sPar[64];
  __shared__ float sPv[64];

  const int tid = threadIdx.x;
  const int ty = tid >> 4, tx = tid & 15;
  const int r0 = ty << 2;               // 4 batch rows per thread
  const int lrow = tid >> 2;            // A-loader row (0..63)
  const int lkv = tid & 3;              // A-loader k-vec (float4)

  for (int t = 0; t < LN; ++t) {
    if (t) pass_barrier(pass, 64u);

    if (tid < 64) {
      int b = mb + tid;
      int node, par; float pv;
      if (pass == 0) {
        node = indexes[t * BN + b];
        par  = td_parent_idx[node * BN + b];
        pv   = td_parent_valid[node * BN + b];
      } else {
        node = td_node[t * BN + b];
        par  = td_parent_idx[t * BN + b];
        pv   = td_parent_valid[t * BN + b];
      }
      sNode[tid] = node; sPar[tid] = par; sPv[tid] = pv;
    }
    __syncthreads();

    // A row source for this thread's loader role
    const float* arow;
    bool azero = false;
    {
      int bb = mb + lrow;
      if (pass == 0) {
        arow = g_acc + ((size_t)bb * LN + sNode[lrow]) * HN;   // child sum
      } else {
        arow = g_tds + ((size_t)bb * LN + sPar[lrow]) * HN;    // parent hidden
        azero = (sPv[lrow] == 0.f);                            // root -> h = 0
      }
    }

    float hv[4][3];
#pragma unroll
    for (int j = 0; j < 4; ++j)
#pragma unroll
      for (int g = 0; g < 3; ++g) hv[j][g] = 0.f;

    for (int k0 = 0; k0 < HN; k0 += 16) {
      float4 va = azero ? make_float4(0.f, 0.f, 0.f, 0.f)
                        : *(const float4*)(arow + k0 + (lkv << 2));
      As[(lkv << 2) + 0][lrow] = va.x;
      As[(lkv << 2) + 1][lrow] = va.y;
      As[(lkv << 2) + 2][lrow] = va.z;
      As[(lkv << 2) + 3][lrow] = va.w;
      {
        const float* up = Uh + (size_t)(k0 + ty) * G3 + c0 + tx;
        Bs[ty][tx]      = up[0];      // r third
        Bs[ty][16 + tx] = up[512];    // z third
        Bs[ty][32 + tx] = up[1024];   // n third
      }
      __syncthreads();
#pragma unroll
      for (int k = 0; k < 16; ++k) {
        float a[4];
        *(float4*)&a[0] = *(const float4*)&As[k][r0];
        float b0 = Bs[k][tx], b1 = Bs[k][16 + tx], b2 = Bs[k][32 + tx];
#pragma unroll
        for (int j = 0; j < 4; ++j) {
          hv[j][0] = fmaf(a[j], b0, hv[j][0]);
          hv[j][1] = fmaf(a[j], b1, hv[j][1]);
          hv[j][2] = fmaf(a[j], b2, hv[j][2]);
        }
      }
      __syncthreads();
    }

    // Fused GRU gates + state/output writes.
    // Structural race-freedom: this step reads only row node_t, writes only
    // row parent(node_t) != node_t; (batch, col) tiles are block-disjoint.
    const int ch = c0 + tx;
#pragma unroll
    for (int j = 0; j < 4; ++j) {
      int row = r0 + j;
      int b = mb + row;
      int node = sNode[row];
      size_t pxo = ((size_t)node * BN + b) * G3 + ch;
      float xr = PX[pxo], xz = PX[pxo + 512], xn = PX[pxo + 1024];
      float hprev;
      if (pass == 0) {
        hprev = g_acc[((size_t)b * LN + node) * HN + ch];
      } else {
        hprev = (sPv[row] != 0.f)
              ? g_tds[((size_t)b * LN + sPar[row]) * HN + ch] : 0.f;
      }
      float rg = 1.f / (1.f + expf(-(xr + hv[j][0])));
      float zg = 1.f / (1.f + expf(-(xz + hv[j][1])));
      float ng = tanhf(xn + rg * hv[j][2]);
      float hnew = (1.f - zg) * ng + zg * hprev;

      out[((size_t)b * LN + node) * (2 * HN) + pass * HN + ch] = hnew;
      if (pass == 0) {
        if (sPv[row] != 0.f)   // scatter-add into parent's child-sum slot
          g_acc[((size_t)b * LN + sPar[row]) * HN + ch] += hnew;
      } else {
        g_tds[((size_t)b * LN + node) * HN + ch] = hnew;
      }
    }
  }
}

// ---------------------------------------------------------------------------
// root hidden -> output_t  (d_out tail: [1,B,2H])
// ---------------------------------------------------------------------------
__global__ void copy_root_kernel(const int* __restrict__ root_index,
                                 float* __restrict__ out) {
  int i = blockIdx.x * blockDim.x + threadIdx.x;   // 0 .. 131071
  int b = i >> 10, c = i & 1023;
  int r = root_index[b];
  out[(size_t)BN * LN * 1024 + i] = out[((size_t)b * LN + r) * 1024 + c];
}

// ---------------------------------------------------------------------------
extern "C" void kernel_launch(void* const* d_in, const int* in_sizes, int n_in,
                              void* d_out, int out_size) {
  (void)in_sizes; (void)n_in; (void)out_size;
  const float* emb             = (const float*)d_in[0];
  const int*   indexes         = (const int*)d_in[1];
  /* d_in[2] child_mask unused: replaced by parent scatter-add */
  const int*   td_node         = (const int*)d_in[3];
  const int*   td_parent_idx   = (const int*)d_in[4];
  const float* td_parent_valid = (const float*)d_in[5];
  const int*   root_index      = (const int*)d_in[6];
  const float* dt_Wx           = (const float*)d_in[7];
  const float* dt_Uh           = (const float*)d_in[8];
  const float* dt_b            = (const float*)d_in[9];
  const float* td_Wx           = (const float*)d_in[10];
  const float* td_Uh           = (const float*)d_in[11];
  const float* td_b            = (const float*)d_in[12];
  float* out = (float*)d_out;

  zero_acc_kernel<<<16384, 256>>>();

  dim3 gg(G3 / 128, (LN * BN) / 128);
  sgemm_px<<<gg, 256>>>(emb, dt_Wx, dt_b, 0);
  sgemm_px<<<gg, 256>>>(emb, td_Wx, td_b, 1);

  recurrent_kernel<<<128, 256>>>(indexes, td_node, td_parent_idx,
                                 td_parent_valid, dt_Uh, td_Uh, out);

  copy_root_kernel<<<128, 1024>>>(root_index, out);
}

// round 2
// speedup vs baseline: 1.9123x; 1.9123x over previous
#include <cuda_runtime.h>
#include <cstdint>
#include <cstddef>

#define LN 256
#define BN 128
#define DN 512
#define HN 512
#define G3 1536
#define NPASSBLK 148   // blocks per pass in wavefront kernel

// ---- scratch (static device globals; no allocations allowed) ----
static __device__ float g_PXdt[(size_t)LN * BN * G3];   // emb @ dt_Wx + b  [node,B,3H]
static __device__ float g_PXtd[(size_t)LN * BN * G3];   // emb @ td_Wx + b
static __device__ float g_acc[(size_t)BN * LN * HN];    // dt child-sum accumulator [B,L,H]
static __device__ float g_tds[(size_t)BN * LN * HN];    // td hidden state [B,L,H]
static __device__ int   g_lvl[2][BN][LN];               // wavefront level per cell
static __device__ int   g_hist[2][257];
static __device__ int   g_off[2][258];
static __device__ int   g_pos[2][257];
static __device__ int   g_maxlvl[2];
static __device__ int   g_sched[2][(size_t)BN * LN];    // (b<<8)|node, level-sorted
static __device__ unsigned g_barCount[2];
static __device__ volatile unsigned g_barGen[2];

// ---------------------------------------------------------------------------
__global__ void zero_acc_kernel() {
  size_t i = (size_t)blockIdx.x * blockDim.x + threadIdx.x;
  reinterpret_cast<float4*>(g_acc)[i] = make_float4(0.f, 0.f, 0.f, 0.f);
}

__global__ void zero_meta_kernel() {
  int t = threadIdx.x;           // 1 block, 1024 threads
  if (t < 2 * 257) ((int*)g_hist)[t] = 0;
  if (t < 2) g_maxlvl[t] = 0;
}

// ---------------------------------------------------------------------------
// per-batch tree level computation (dt: height from leaves, td: depth)
// parent(i,b) = par[i*BN+b]; pv==0 only at root. head[i] < i (data property).
// ---------------------------------------------------------------------------
__global__ void levels_kernel(const int* __restrict__ par,
                              const float* __restrict__ pv) {
  int tid = threadIdx.x;         // 256 threads: (pass, batch)
  int pass = tid >> 7, b = tid & 127;
  int lvl[LN];
  if (pass == 0) {
#pragma unroll 4
    for (int i = 0; i < LN; ++i) lvl[i] = 0;
    for (int i = LN - 1; i >= 1; --i) {
      int p = par[i * BN + b];
      float v = pv[i * BN + b];
      if (v != 0.f) { int c = lvl[i] + 1; if (c > lvl[p]) lvl[p] = c; }
    }
  } else {
    for (int i = 0; i < LN; ++i) {
      float v = pv[i * BN + b];
      int p = par[i * BN + b];
      lvl[i] = (v != 0.f) ? (lvl[p] + 1) : 0;
    }
  }
  int mx = 0;
  for (int i = 0; i < LN; ++i) {
    int l = lvl[i];
    g_lvl[pass][b][i] = l;
    atomicAdd(&g_hist[pass][l], 1);
    if (l > mx) mx = l;
  }
  atomicMax(&g_maxlvl[pass], mx);
}

__global__ void scan_kernel() {
  int p = threadIdx.x;
  if (p < 2) {
    int s = 0;
    for (int l = 0; l <= 256; ++l) {
      g_off[p][l] = s; g_pos[p][l] = s;
      if (l < 256) s += g_hist[p][l];
    }
    g_off[p][257] = s;
  }
}

__global__ void scatter_kernel() {
  int e = blockIdx.x * blockDim.x + threadIdx.x;   // 65536
  int pass = e >> 15, b = (e >> 8) & 127, node = e & 255;
  int l = g_lvl[pass][b][node];
  int pos = atomicAdd(&g_pos[pass][l], 1);
  g_sched[pass][pos] = (b << 8) | node;
}

// ---------------------------------------------------------------------------
// SGEMM: C[M,1536] = A[M,512] @ W[512,1536] + bias  (128x128x16 tiles, fp32)
// ---------------------------------------------------------------------------
__global__ void __launch_bounds__(256) sgemm_px(
    const float* __restrict__ A, const float* __restrict__ W,
    const float* __restrict__ bias, int which)
{
  float* __restrict__ C = which ? g_PXtd : g_PXdt;
  __shared__ float As[16][132];
  __shared__ float Bs[16][128];
  const int m0 = blockIdx.y << 7;
  const int n0 = blockIdx.x << 7;
  const int tid = threadIdx.x;
  const int ty = tid >> 4, tx = tid & 15;

  float acc[8][8];
#pragma unroll
  for (int i = 0; i < 8; ++i)
#pragma unroll
    for (int j = 0; j < 8; ++j) acc[i][j] = 0.f;

  for (int k0 = 0; k0 < DN; k0 += 16) {
#pragma unroll
    for (int i = 0; i < 2; ++i) {
      int idx = tid + (i << 8);
      int row = idx >> 2, kv = idx & 3;
      float4 va = *(const float4*)(A + (size_t)(m0 + row) * DN + k0 + (kv << 2));
      As[(kv << 2) + 0][row] = va.x;
      As[(kv << 2) + 1][row] = va.y;
      As[(kv << 2) + 2][row] = va.z;
      As[(kv << 2) + 3][row] = va.w;
      int kk = idx >> 5, cv = idx & 31;
      *(float4*)&Bs[kk][cv << 2] =
          *(const float4*)(W + (size_t)(k0 + kk) * G3 + n0 + (cv << 2));
    }
    __syncthreads();
#pragma unroll
    for (int k = 0; k < 16; ++k) {
      float a[8], b[8];
      *(float4*)&a[0] = *(const float4*)&As[k][(ty << 3)];
      *(float4*)&a[4] = *(const float4*)&As[k][(ty << 3) + 4];
      *(float4*)&b[0] = *(const float4*)&Bs[k][(tx << 3)];
      *(float4*)&b[4] = *(const float4*)&Bs[k][(tx << 3) + 4];
#pragma unroll
      for (int i = 0; i < 8; ++i)
#pragma unroll
        for (int j = 0; j < 8; ++j)
          acc[i][j] = fmaf(a[i], b[j], acc[i][j]);
    }
    __syncthreads();
  }
#pragma unroll
  for (int i = 0; i < 8; ++i) {
    size_t row = (size_t)m0 + (ty << 3) + i;
    float* cp = C + row * G3 + n0 + (tx << 3);
#pragma unroll
    for (int j = 0; j < 8; ++j)
      cp[j] = acc[i][j] + bias[n0 + (tx << 3) + j];
  }
}

// ---------------------------------------------------------------------------
__device__ __forceinline__ void pass_barrier(int p, unsigned nb) {
  __syncthreads();
  if (threadIdx.x == 0) {
    __threadfence();
    unsigned g = g_barGen[p];
    unsigned a = atomicAdd(&g_barCount[p], 1u);
    if (a == nb - 1u) {
      g_barCount[p] = 0u;
      __threadfence();
      g_barGen[p] = g + 1u;
    } else {
      while (g_barGen[p] == g) { }
      __threadfence();
    }
  }
  __syncthreads();
}

// ---------------------------------------------------------------------------
// Wavefront recurrent kernel: 296 blocks (148 dt + 148 td), 256 threads.
// Per level: big gathered GEMM [R x 1536] = H_rows @ Uh, fused GRU epilogue.
// Tile = 64 rows x 64 hidden cols (x3 gates = 192 GEMM cols), K=512.
// Thread microtile: 8 rows x (2 hidden cols x 3 gates) = 48 FMA / 56B LDS.
// ---------------------------------------------------------------------------
__global__ void __launch_bounds__(256, 2) wavefront_kernel(
    const int* __restrict__ par, const float* __restrict__ pvv,
    const float* __restrict__ dt_Uh, const float* __restrict__ td_Uh,
    float* __restrict__ out)
{
  const int pass = (blockIdx.x >= NPASSBLK) ? 1 : 0;
  const int pid = blockIdx.x - pass * NPASSBLK;
  const float* __restrict__ Uh = pass ? td_Uh : dt_Uh;
  const float* __restrict__ PX = pass ? g_PXtd : g_PXdt;

  __shared__ float As[16][68];
  __shared__ float Bs[16][192];
  __shared__ int sB[64], sNode[64], sPar[64];
  __shared__ float sPv[64];
  __shared__ const float* sArow[64];
  __shared__ unsigned char sValid[64];

  const int tid = threadIdx.x;
  const int tx = tid & 31, ty = tid >> 5;
  const int lrow = tid >> 2, lkv = tid & 3;

  // Bs loader precompute: 3 float4s per thread per k-tile
  int bs_k[3]; size_t bs_src[3]; float* bs_dst[3];
#pragma unroll
  for (int q = 0; q < 3; ++q) {
    int f4 = tid + (q << 8);         // 0..767 of 48 float4/k * 16 k
    int kk = f4 / 48;
    int rem = f4 - kk * 48;
    int g = rem >> 4;
    int c4 = (rem & 15) << 2;
    bs_k[q] = kk;
    bs_src[q] = (size_t)kk * G3 + g * 512 + c4;
    bs_dst[q] = &Bs[kk][g * 64 + c4];
  }
  float* as_dst = &As[lkv << 2][lrow];

  const int nlvl = g_maxlvl[pass] + 1;
  for (int l = 0; l < nlvl; ++l) {
    const int beg = g_off[pass][l], end = g_off[pass][l + 1];
    const int R = end - beg;
    const int ntile = ((R + 63) >> 6) << 3;      // rowtiles * 8 coltiles

    for (int tix = pid; tix < ntile; tix += NPASSBLK) {
      const int rt = tix >> 3, ct = tix & 7;
      const int c0 = ct << 6;
      const int rowBase = beg + (rt << 6);

      if (tid < 64) {
        int rr = rowBase + tid;
        int valid = rr < end;
        int ent = g_sched[pass][valid ? rr : rowBase];
        int b = ent >> 8, node = ent & 255;
        sB[tid] = b; sNode[tid] = node;
        int p = par[node * BN + b];
        float v = pvv[node * BN + b];
        sPar[tid] = p; sPv[tid] = v;
        sValid[tid] = (unsigned char)valid;
        const float* ar;
        bool zero = !valid;
        if (pass == 0) ar = g_acc + ((size_t)b * LN + node) * HN;
        else { ar = g_tds + ((size_t)b * LN + p) * HN; zero |= (v == 0.f); }
        sArow[tid] = zero ? nullptr : ar;
      }
      __syncthreads();

      const float* arow = sArow[lrow];

      float acc[8][6];
#pragma unroll
      for (int j = 0; j < 8; ++j)
#pragma unroll
        for (int g = 0; g < 6; ++g) acc[j][g] = 0.f;

      for (int k0 = 0; k0 < HN; k0 += 16) {
        float4 va = arow ? *(const float4*)(arow + k0 + (lkv << 2))
                         : make_float4(0.f, 0.f, 0.f, 0.f);
        as_dst[0]       = va.x;
        as_dst[68]      = va.y;
        as_dst[136]     = va.z;
        as_dst[204]     = va.w;
        const size_t kadd = (size_t)k0 * G3 + c0;
#pragma unroll
        for (int q = 0; q < 3; ++q)
          *(float4*)bs_dst[q] = *(const float4*)(Uh + bs_src[q] + kadd);
        __syncthreads();
#pragma unroll
        for (int k = 0; k < 16; ++k) {
          float a[8];
          *(float4*)&a[0] = *(const float4*)&As[k][ty << 3];
          *(float4*)&a[4] = *(const float4*)&As[k][(ty << 3) + 4];
          float2 b0 = *(const float2*)&Bs[k][tx << 1];
          float2 b1 = *(const float2*)&Bs[k][64 + (tx << 1)];
          float2 b2 = *(const float2*)&Bs[k][128 + (tx << 1)];
#pragma unroll
          for (int j = 0; j < 8; ++j) {
            acc[j][0] = fmaf(a[j], b0.x, acc[j][0]);
            acc[j][1] = fmaf(a[j], b0.y, acc[j][1]);
            acc[j][2] = fmaf(a[j], b1.x, acc[j][2]);
            acc[j][3] = fmaf(a[j], b1.y, acc[j][3]);
            acc[j][4] = fmaf(a[j], b2.x, acc[j][4]);
            acc[j][5] = fmaf(a[j], b2.y, acc[j][5]);
          }
        }
        __syncthreads();
      }

      // fused GRU epilogue
      const int chb = c0 + (tx << 1);
#pragma unroll
      for (int j = 0; j < 8; ++j) {
        int rloc = (ty << 3) + j;
        if (!sValid[rloc]) continue;
        int b = sB[rloc], node = sNode[rloc];
        size_t pxo = ((size_t)node * BN + b) * G3 + chb;
        float2 xr = *(const float2*)&PX[pxo];
        float2 xz = *(const float2*)&PX[pxo + 512];
        float2 xn = *(const float2*)&PX[pxo + 1024];
        float2 hp;
        if (pass == 0) {
          hp = *(const float2*)&g_acc[((size_t)b * LN + node) * HN + chb];
        } else if (sPv[rloc] != 0.f) {
          hp = *(const float2*)&g_tds[((size_t)b * LN + sPar[rloc]) * HN + chb];
        } else hp = make_float2(0.f, 0.f);

        float rg0 = 1.f / (1.f + expf(-(xr.x + acc[j][0])));
        float rg1 = 1.f / (1.f + expf(-(xr.y + acc[j][1])));
        float zg0 = 1.f / (1.f + expf(-(xz.x + acc[j][2])));
        float zg1 = 1.f / (1.f + expf(-(xz.y + acc[j][3])));
        float ng0 = tanhf(xn.x + rg0 * acc[j][4]);
        float ng1 = tanhf(xn.y + rg1 * acc[j][5]);
        float h0 = (1.f - zg0) * ng0 + zg0 * hp.x;
        float h1 = (1.f - zg1) * ng1 + zg1 * hp.y;

        float* op = &out[((size_t)b * LN + node) * (2 * HN) + pass * HN + chb];
        *(float2*)op = make_float2(h0, h1);
        if (pass == 0) {
          if (sPv[rloc] != 0.f) {
            float* dst = &g_acc[((size_t)b * LN + sPar[rloc]) * HN + chb];
            atomicAdd(dst, h0);
            atomicAdd(dst + 1, h1);
          }
        } else {
          *(float2*)&g_tds[((size_t)b * LN + node) * HN + chb] =
              make_float2(h0, h1);
        }
      }
      __syncthreads();
    }
    pass_barrier(pass, NPASSBLK);
  }
}

// ---------------------------------------------------------------------------
__global__ void copy_root_kernel(const int* __restrict__ root_index,
                                 float* __restrict__ out) {
  int i = blockIdx.x * blockDim.x + threadIdx.x;   // 0 .. 131071
  int b = i >> 10, c = i & 1023;
  int r = root_index[b];
  out[(size_t)BN * LN * 1024 + i] = out[((size_t)b * LN + r) * 1024 + c];
}

// ---------------------------------------------------------------------------
extern "C" void kernel_launch(void* const* d_in, const int* in_sizes, int n_in,
                              void* d_out, int out_size) {
  (void)in_sizes; (void)n_in; (void)out_size;
  const float* emb             = (const float*)d_in[0];
  /* d_in[1] indexes, d_in[2] child_mask, d_in[3] td_node: unused
     (schedule is rebuilt from parent pointers) */
  const int*   td_parent_idx   = (const int*)d_in[4];
  const float* td_parent_valid = (const float*)d_in[5];
  const int*   root_index      = (const int*)d_in[6];
  const float* dt_Wx           = (const float*)d_in[7];
  const float* dt_Uh           = (const float*)d_in[8];
  const float* dt_b            = (const float*)d_in[9];
  const float* td_Wx           = (const float*)d_in[10];
  const float* td_Uh           = (const float*)d_in[11];
  const float* td_b            = (const float*)d_in[12];
  float* out = (float*)d_out;

  zero_acc_kernel<<<16384, 256>>>();
  zero_meta_kernel<<<1, 1024>>>();
  levels_kernel<<<1, 256>>>(td_parent_idx, td_parent_valid);
  scan_kernel<<<1, 32>>>();
  scatter_kernel<<<64, 1024>>>();

  dim3 gg(G3 / 128, (LN * BN) / 128);
  sgemm_px<<<gg, 256>>>(emb, dt_Wx, dt_b, 0);
  sgemm_px<<<gg, 256>>>(emb, td_Wx, td_b, 1);

  wavefront_kernel<<<2 * NPASSBLK, 256>>>(td_parent_idx, td_parent_valid,
                                          dt_Uh, td_Uh, out);

  copy_root_kernel<<<128, 1024>>>(root_index, out);
}

// round 4
// speedup vs baseline: 3.8196x; 1.9974x over previous
#include <cuda_runtime.h>
#include <cstdint>
#include <cstddef>

#define LN 256
#define BN 128
#define DN 512
#define HN 512
#define G3 1536
#define NPASSBLK 148

// ---- scratch (static device globals; no allocations allowed) ----
static __device__ float g_PXdt[(size_t)LN * BN * G3];
static __device__ float g_PXtd[(size_t)LN * BN * G3];
static __device__ float g_acc[(size_t)BN * LN * HN];
static __device__ float g_tds[(size_t)BN * LN * HN];
static __device__ int   g_lvl[2][BN][LN];
static __device__ int   g_hist[2][257];
static __device__ int   g_off[2][258];
static __device__ int   g_pos[2][257];
static __device__ int   g_maxlvl[2];
static __device__ int   g_sched[2][(size_t)BN * LN];
static __device__ unsigned g_barCount[2];
static __device__ volatile unsigned g_barGen[2];

// ---------------------------------------------------------------------------
__device__ __forceinline__ uint32_t f2tf32(float x) {
  uint32_t u;
  asm("cvt.rna.tf32.f32 %0, %1;" : "=r"(u) : "f"(x));
  return u;
}

__device__ __forceinline__ void mma8(float d[4], const uint32_t a[4],
                                     const uint32_t b[2]) {
  asm volatile(
      "mma.sync.aligned.m16n8k8.row.col.f32.tf32.tf32.f32 "
      "{%0,%1,%2,%3},{%4,%5,%6,%7},{%8,%9},{%0,%1,%2,%3};"
      : "+f"(d[0]), "+f"(d[1]), "+f"(d[2]), "+f"(d[3])
      : "r"(a[0]), "r"(a[1]), "r"(a[2]), "r"(a[3]), "r"(b[0]), "r"(b[1]));
}

// ---------------------------------------------------------------------------
__global__ void zero_acc_kernel() {
  size_t i = (size_t)blockIdx.x * blockDim.x + threadIdx.x;
  reinterpret_cast<float4*>(g_acc)[i] = make_float4(0.f, 0.f, 0.f, 0.f);
}

__global__ void zero_meta_kernel() {
  int t = threadIdx.x;
  if (t < 2 * 257) ((int*)g_hist)[t] = 0;
  if (t < 2) g_maxlvl[t] = 0;
}

__global__ void levels_kernel(const int* __restrict__ par,
                              const float* __restrict__ pv) {
  int tid = threadIdx.x;         // 256 threads: (pass, batch)
  int pass = tid >> 7, b = tid & 127;
  int lvl[LN];
  if (pass == 0) {
#pragma unroll 4
    for (int i = 0; i < LN; ++i) lvl[i] = 0;
    for (int i = LN - 1; i >= 1; --i) {
      int p = par[i * BN + b];
      float v = pv[i * BN + b];
      if (v != 0.f) { int c = lvl[i] + 1; if (c > lvl[p]) lvl[p] = c; }
    }
  } else {
    for (int i = 0; i < LN; ++i) {
      float v = pv[i * BN + b];
      int p = par[i * BN + b];
      lvl[i] = (v != 0.f) ? (lvl[p] + 1) : 0;
    }
  }
  int mx = 0;
  for (int i = 0; i < LN; ++i) {
    int l = lvl[i];
    g_lvl[pass][b][i] = l;
    atomicAdd(&g_hist[pass][l], 1);
    if (l > mx) mx = l;
  }
  atomicMax(&g_maxlvl[pass], mx);
}

__global__ void scan_kernel() {
  int p = threadIdx.x;
  if (p < 2) {
    int s = 0;
    for (int l = 0; l <= 256; ++l) {
      g_off[p][l] = s; g_pos[p][l] = s;
      if (l < 256) s += g_hist[p][l];
    }
    g_off[p][257] = s;
  }
}

__global__ void scatter_kernel() {
  int e = blockIdx.x * blockDim.x + threadIdx.x;
  int pass = e >> 15, b = (e >> 8) & 127, node = e & 255;
  int l = g_lvl[pass][b][node];
  int pos = atomicAdd(&g_pos[pass][l], 1);
  g_sched[pass][pos] = (b << 8) | node;
}

// ---------------------------------------------------------------------------
// TF32 SGEMM: C[M,1536] = A[M,512] @ W[512,1536] + bias
// 128x128x16 tiles, 8 warps, warp tile 32x64 (m16n8k8 frags)
// ---------------------------------------------------------------------------
__global__ void __launch_bounds__(256, 2) sgemm_px_tf32(
    const float* __restrict__ A, const float* __restrict__ W,
    const float* __restrict__ bias, int which)
{
  float* __restrict__ C = which ? g_PXtd : g_PXdt;
  __shared__ uint32_t As[16][136];   // [k][m], 136 mod 32 == 8 -> frag-LDS conflict-free
  __shared__ uint32_t Bs[16][136];   // [k][n]
  const int m0 = blockIdx.y << 7;
  const int n0 = blockIdx.x << 7;
  const int tid = threadIdx.x;
  const int warp = tid >> 5, lane = tid & 31;
  const int q = lane & 3, g = lane >> 2;
  const int mb = (warp >> 1) << 5;   // 0,32,64,96
  const int nb = (warp & 1) << 6;    // 0,64

  float acc[2][8][4];
#pragma unroll
  for (int i = 0; i < 2; ++i)
#pragma unroll
    for (int j = 0; j < 8; ++j)
#pragma unroll
      for (int c = 0; c < 4; ++c) acc[i][j][c] = 0.f;

  for (int k0 = 0; k0 < DN; k0 += 16) {
#pragma unroll
    for (int i = 0; i < 2; ++i) {
      int idx = tid + (i << 8);
      int row = idx >> 2, kv = idx & 3;
      float4 va = *(const float4*)(A + (size_t)(m0 + row) * DN + k0 + (kv << 2));
      As[(kv << 2) + 0][row] = f2tf32(va.x);
      As[(kv << 2) + 1][row] = f2tf32(va.y);
      As[(kv << 2) + 2][row] = f2tf32(va.z);
      As[(kv << 2) + 3][row] = f2tf32(va.w);
      int kk = idx >> 5, c4 = (idx & 31) << 2;
      float4 vb = *(const float4*)(W + (size_t)(k0 + kk) * G3 + n0 + c4);
      Bs[kk][c4 + 0] = f2tf32(vb.x);
      Bs[kk][c4 + 1] = f2tf32(vb.y);
      Bs[kk][c4 + 2] = f2tf32(vb.z);
      Bs[kk][c4 + 3] = f2tf32(vb.w);
    }
    __syncthreads();

    uint32_t afr[2][2][4], bfr[2][8][2];
#pragma unroll
    for (int ks = 0; ks < 2; ++ks) {
      int kq = (ks << 3) + q;
#pragma unroll
      for (int i = 0; i < 2; ++i) {
        int rb = mb + (i << 4);
        afr[ks][i][0] = As[kq][rb + g];
        afr[ks][i][1] = As[kq][rb + g + 8];
        afr[ks][i][2] = As[kq + 4][rb + g];
        afr[ks][i][3] = As[kq + 4][rb + g + 8];
      }
#pragma unroll
      for (int j = 0; j < 8; ++j) {
        int cc = nb + (j << 3) + g;
        bfr[ks][j][0] = Bs[kq][cc];
        bfr[ks][j][1] = Bs[kq + 4][cc];
      }
    }
#pragma unroll
    for (int ks = 0; ks < 2; ++ks)
#pragma unroll
      for (int i = 0; i < 2; ++i)
#pragma unroll
        for (int j = 0; j < 8; ++j)
          mma8(acc[i][j], afr[ks][i], bfr[ks][j]);
    __syncthreads();
  }

#pragma unroll
  for (int i = 0; i < 2; ++i) {
    int r0 = m0 + mb + (i << 4) + g;
#pragma unroll
    for (int j = 0; j < 8; ++j) {
      int col = n0 + nb + (j << 3) + (q << 1);
      float bx = bias[col], by = bias[col + 1];
      *(float2*)&C[(size_t)r0 * G3 + col] =
          make_float2(acc[i][j][0] + bx, acc[i][j][1] + by);
      *(float2*)&C[(size_t)(r0 + 8) * G3 + col] =
          make_float2(acc[i][j][2] + bx, acc[i][j][3] + by);
    }
  }
}

// ---------------------------------------------------------------------------
__device__ __forceinline__ void pass_barrier(int p, unsigned nb) {
  __syncthreads();
  if (threadIdx.x == 0) {
    __threadfence();
    unsigned g = g_barGen[p];
    unsigned a = atomicAdd(&g_barCount[p], 1u);
    if (a == nb - 1u) {
      g_barCount[p] = 0u;
      __threadfence();
      g_barGen[p] = g + 1u;
    } else {
      while (g_barGen[p] == g) { __nanosleep(20); }
      __threadfence();
    }
  }
  __syncthreads();
}

// ---------------------------------------------------------------------------
// TF32 wavefront kernel: 296 blocks (148/pass), 256 threads = 8 warps.
// Block tile: 64 gathered rows x (3 gates x 64 hidden cols), K = 512.
// Warp tile 32x48: 2 m-frags x 6 n-frags (gate-blocked cols).
// ---------------------------------------------------------------------------
__global__ void __launch_bounds__(256, 2) wavefront_kernel(
    const int* __restrict__ par, const float* __restrict__ pvv,
    const float* __restrict__ dt_Uh, const float* __restrict__ td_Uh,
    float* __restrict__ out)
{
  const int pass = (blockIdx.x >= NPASSBLK) ? 1 : 0;
  const int pid = blockIdx.x - pass * NPASSBLK;
  const float* __restrict__ Uh = pass ? td_Uh : dt_Uh;
  const float* __restrict__ PX = pass ? g_PXtd : g_PXdt;

  __shared__ uint32_t As[16][72];    // [k][row], 72 mod 32 == 8
  __shared__ uint32_t Bs[16][200];   // [k][gate*64 + c], 200 mod 32 == 8
  __shared__ int sB[64], sNode[64], sPar[64];
  __shared__ float sPv[64];
  __shared__ const float* sArow[64];
  __shared__ unsigned char sValid[64];

  const int tid = threadIdx.x;
  const int warp = tid >> 5, lane = tid & 31;
  const int q = lane & 3, g = lane >> 2;
  const int mb = (warp >> 2) << 5;   // 0 or 32
  const int hb = (warp & 3) << 4;    // hidden col base within 64: 0,16,32,48
  const int lrow = tid >> 2, lkv = tid & 3;

  const int nlvl = g_maxlvl[pass] + 1;
  for (int l = 0; l < nlvl; ++l) {
    const int beg = g_off[pass][l], end = g_off[pass][l + 1];
    const int R = end - beg;
    const int ntile = ((R + 63) >> 6) << 3;   // rowtiles * 8 hidden-col tiles

    for (int tix = pid; tix < ntile; tix += NPASSBLK) {
      const int rt = tix >> 3, ct = tix & 7;
      const int c0 = ct << 6;                 // hidden col tile base
      const int rowBase = beg + (rt << 6);

      if (tid < 64) {
        int rr = rowBase + tid;
        int valid = rr < end;
        int ent = g_sched[pass][valid ? rr : rowBase];
        int b = ent >> 8, node = ent & 255;
        sB[tid] = b; sNode[tid] = node;
        int p = par[node * BN + b];
        float v = pvv[node * BN + b];
        sPar[tid] = p; sPv[tid] = v;
        sValid[tid] = (unsigned char)valid;
        const float* ar;
        bool zero = !valid;
        if (pass == 0) ar = g_acc + ((size_t)b * LN + node) * HN;
        else { ar = g_tds + ((size_t)b * LN + p) * HN; zero |= (v == 0.f); }
        sArow[tid] = zero ? nullptr : ar;
      }
      __syncthreads();

      const float* arow = sArow[lrow];

      float acc[2][6][4];
#pragma unroll
      for (int i = 0; i < 2; ++i)
#pragma unroll
        for (int j = 0; j < 6; ++j)
#pragma unroll
          for (int c = 0; c < 4; ++c) acc[i][j][c] = 0.f;

      for (int k0 = 0; k0 < HN; k0 += 16) {
        float4 va = arow ? *(const float4*)(arow + k0 + (lkv << 2))
                         : make_float4(0.f, 0.f, 0.f, 0.f);
        As[(lkv << 2) + 0][lrow] = f2tf32(va.x);
        As[(lkv << 2) + 1][lrow] = f2tf32(va.y);
        As[(lkv << 2) + 2][lrow] = f2tf32(va.z);
        As[(lkv << 2) + 3][lrow] = f2tf32(va.w);
#pragma unroll
        for (int qq = 0; qq < 3; ++qq) {
          int f4 = tid + (qq << 8);            // 768 float4 = 16k x 48
          int kk = f4 / 48;
          int rem = f4 - kk * 48;
          int gate = rem >> 4;
          int c4 = (rem & 15) << 2;
          float4 vb = *(const float4*)(Uh + (size_t)(k0 + kk) * G3 +
                                       gate * 512 + c0 + c4);
          uint32_t* d = &Bs[kk][(gate << 6) + c4];
          d[0] = f2tf32(vb.x); d[1] = f2tf32(vb.y);
          d[2] = f2tf32(vb.z); d[3] = f2tf32(vb.w);
        }
        __syncthreads();

        uint32_t afr[2][2][4], bfr[2][6][2];
#pragma unroll
        for (int ks = 0; ks < 2; ++ks) {
          int kq = (ks << 3) + q;
#pragma unroll
          for (int i = 0; i < 2; ++i) {
            int rb = mb + (i << 4);
            afr[ks][i][0] = As[kq][rb + g];
            afr[ks][i][1] = As[kq][rb + g + 8];
            afr[ks][i][2] = As[kq + 4][rb + g];
            afr[ks][i][3] = As[kq + 4][rb + g + 8];
          }
#pragma unroll
          for (int j = 0; j < 6; ++j) {
            int cc = ((j >> 1) << 6) + hb + ((j & 1) << 3) + g;
            bfr[ks][j][0] = Bs[kq][cc];
            bfr[ks][j][1] = Bs[kq + 4][cc];
          }
        }
#pragma unroll
        for (int ks = 0; ks < 2; ++ks)
#pragma unroll
          for (int i = 0; i < 2; ++i)
#pragma unroll
            for (int j = 0; j < 6; ++j)
              mma8(acc[i][j], afr[ks][i], bfr[ks][j]);
        __syncthreads();
      }

      // fused GRU epilogue: thread covers rows {mb+i*16+g(+8)}, cols hb+s*8+2q(+1)
#pragma unroll
      for (int i = 0; i < 2; ++i) {
#pragma unroll
        for (int h = 0; h < 2; ++h) {
          int rloc = mb + (i << 4) + g + (h << 3);
          if (!sValid[rloc]) continue;
          int b = sB[rloc], node = sNode[rloc];
          size_t pxo = ((size_t)node * BN + b) * G3;
          size_t hbase = ((size_t)b * LN + node) * HN;
          float* obase = &out[((size_t)b * LN + node) * (2 * HN) + pass * HN];
#pragma unroll
          for (int s = 0; s < 2; ++s) {
            int ch = c0 + hb + (s << 3) + (q << 1);
            int ci = h << 1;
            float hr0 = acc[i][s][ci],     hr1 = acc[i][s][ci + 1];
            float hz0 = acc[i][2 + s][ci], hz1 = acc[i][2 + s][ci + 1];
            float hn0 = acc[i][4 + s][ci], hn1 = acc[i][4 + s][ci + 1];
            float2 xr = *(const float2*)&PX[pxo + ch];
            float2 xz = *(const float2*)&PX[pxo + 512 + ch];
            float2 xn = *(const float2*)&PX[pxo + 1024 + ch];
            float2 hp;
            if (pass == 0) {
              hp = *(const float2*)&g_acc[hbase + ch];
            } else if (sPv[rloc] != 0.f) {
              hp = *(const float2*)&g_tds[((size_t)b * LN + sPar[rloc]) * HN + ch];
            } else hp = make_float2(0.f, 0.f);

            float rg0 = 1.f / (1.f + expf(-(xr.x + hr0)));
            float rg1 = 1.f / (1.f + expf(-(xr.y + hr1)));
            float zg0 = 1.f / (1.f + expf(-(xz.x + hz0)));
            float zg1 = 1.f / (1.f + expf(-(xz.y + hz1)));
            float ng0 = tanhf(xn.x + rg0 * hn0);
            float ng1 = tanhf(xn.y + rg1 * hn1);
            float h0 = (1.f - zg0) * ng0 + zg0 * hp.x;
            float h1 = (1.f - zg1) * ng1 + zg1 * hp.y;

            *(float2*)&obase[ch] = make_float2(h0, h1);
            if (pass == 0) {
              if (sPv[rloc] != 0.f) {
                float* dst = &g_acc[((size_t)b * LN + sPar[rloc]) * HN + ch];
                atomicAdd(dst, h0);
                atomicAdd(dst + 1, h1);
              }
            } else {
              *(float2*)&g_tds[hbase + ch] = make_float2(h0, h1);
            }
          }
        }
      }
      __syncthreads();
    }
    pass_barrier(pass, NPASSBLK);
  }
}

// ---------------------------------------------------------------------------
__global__ void copy_root_kernel(const int* __restrict__ root_index,
                                 float* __restrict__ out) {
  int i = blockIdx.x * blockDim.x + threadIdx.x;
  int b = i >> 10, c = i & 1023;
  int r = root_index[b];
  out[(size_t)BN * LN * 1024 + i] = out[((size_t)b * LN + r) * 1024 + c];
}

// ---------------------------------------------------------------------------
extern "C" void kernel_launch(void* const* d_in, const int* in_sizes, int n_in,
                              void* d_out, int out_size) {
  (void)in_sizes; (void)n_in; (void)out_size;
  const float* emb             = (const float*)d_in[0];
  const int*   td_parent_idx   = (const int*)d_in[4];
  const float* td_parent_valid = (const float*)d_in[5];
  const int*   root_index      = (const int*)d_in[6];
  const float* dt_Wx           = (const float*)d_in[7];
  const float* dt_Uh           = (const float*)d_in[8];
  const float* dt_b            = (const float*)d_in[9];
  const float* td_Wx           = (const float*)d_in[10];
  const float* td_Uh           = (const float*)d_in[11];
  const float* td_b            = (const float*)d_in[12];
  float* out = (float*)d_out;

  zero_acc_kernel<<<16384, 256>>>();
  zero_meta_kernel<<<1, 1024>>>();
  levels_kernel<<<1, 256>>>(td_parent_idx, td_parent_valid);
  scan_kernel<<<1, 32>>>();
  scatter_kernel<<<64, 1024>>>();

  dim3 gg(G3 / 128, (LN * BN) / 128);
  sgemm_px_tf32<<<gg, 256>>>(emb, dt_Wx, dt_b, 0);
  sgemm_px_tf32<<<gg, 256>>>(emb, td_Wx, td_b, 1);

  wavefront_kernel<<<2 * NPASSBLK, 256>>>(td_parent_idx, td_parent_valid,
                                          dt_Uh, td_Uh, out);

  copy_root_kernel<<<128, 1024>>>(root_index, out);
}